// round 7
// baseline (speedup 1.0000x reference)
#include <cuda_runtime.h>
#include <cuda_fp16.h>
#include <cstdint>

// Problem constants
#define B_   8
#define TGT  256
#define SRC  256
#define DM   512
#define LDIM 256
#define LOGEPS (-18.420680743952367f)   // log(1e-8)

// -------- scratch (device globals; no allocation) --------
__device__ __half g_dt_h[B_ * TGT * LDIM];   // dec @ W1, fp16
__device__ __half g_et_h[B_ * SRC * LDIM];   // enc @ W2, fp16

// ---------------- helpers ----------------
__device__ __forceinline__ unsigned h2tanh(unsigned x) {
    unsigned y;
    asm("tanh.approx.f16x2 %0, %1;" : "=r"(y) : "r"(x));
    return y;
}
__device__ __forceinline__ unsigned h2add(unsigned a, unsigned b) {
    unsigned y;
    asm("add.rn.f16x2 %0, %1, %2;" : "=r"(y) : "r"(a), "r"(b));
    return y;
}
__device__ __forceinline__ float2 h2tof2(unsigned h) {
    float lo, hi;
    asm("{ .reg .b16 l, h;\n\t"
        "  mov.b32 {l, h}, %2;\n\t"
        "  cvt.f32.f16 %0, l;\n\t"
        "  cvt.f32.f16 %1, h; }"
        : "=f"(lo), "=f"(hi) : "r"(h));
    return make_float2(lo, hi);
}
__device__ __forceinline__ unsigned long long fma2(unsigned long long a,
                                                   unsigned long long b,
                                                   unsigned long long c) {
    unsigned long long d;
    asm("fma.rn.f32x2 %0, %1, %2, %3;" : "=l"(d) : "l"(a), "l"(b), "l"(c));
    return d;
}
__device__ __forceinline__ void unpk2(unsigned long long v, float& lo, float& hi) {
    asm("mov.b64 {%0, %1}, %2;" : "=f"(lo), "=f"(hi) : "l"(v));
}
__device__ __forceinline__ void cp_async16(void* smem_dst, const void* gmem_src) {
    unsigned saddr = (unsigned)__cvta_generic_to_shared(smem_dst);
    asm volatile("cp.async.ca.shared.global [%0], [%1], 16;"
                 :: "r"(saddr), "l"(gmem_src));
}
__device__ __forceinline__ void cp_commit() {
    asm volatile("cp.async.commit_group;" ::: "memory");
}
__device__ __forceinline__ void cp_wait0() {
    asm volatile("cp.async.wait_group 0;" ::: "memory");
}

// =====================================================================
// Kernel A: Yh = fp16(X @ W).  X:[2048,512] W:[512,256]
// 128x64 tile, BK=16, 512 threads, 4m x 4n per thread.
// Duplicated-A smem: As[k][2m]=As[k][2m+1]=A[m][k] so LDS.64 yields the
// packed (a,a) operand for fma.rn.f32x2 with zero MOVs.
// Double-buffered smem, register prefetch, 1 barrier per k-tile.
// Grid (4, 16, 2) = 128 blocks.
// =====================================================================
#define ADUP 520   // floats per As k-row (256 dup m + pad 8); even -> 8B aligned
#define BPAD 68

__global__ __launch_bounds__(512) void gemm_kernel(
    const float* __restrict__ dec, const float* __restrict__ enc,
    const float* __restrict__ W1,  const float* __restrict__ W2)
{
    const float* X; const float* W; __half* Y;
    if (blockIdx.z == 0) { X = dec; W = W1; Y = g_dt_h; }
    else                 { X = enc; W = W2; Y = g_et_h; }

    __shared__ float As[2][16 * ADUP / 2];   // 16 k-rows x 260 floats... see note
    // NOTE: we need 16 rows x (256+4) floats = 4160 per buffer. Use stride 260.
#undef ADUP
#define ADUP 260
    __shared__ float Bs[2][16 * BPAD];

    const int tid = threadIdx.x;
    const int tx  = tid & 15;          // n (x4)
    const int ty  = tid >> 4;          // m (x4), 0..31
    const int m0  = blockIdx.y * 128;
    const int n0  = blockIdx.x * 64;

    // A: 128 rows x 16 k = 512 float4; 1 per thread
    const int am = tid >> 2;           // 0..127
    const int ak = (tid & 3) * 4;      // 0,4,8,12
    // B: 16 k x 64 n = 256 float4; threads 0..255
    const int bk = tid >> 4;           // (only valid for tid<256)
    const int bn = (tid & 15) * 4;

    const float* Ag = X + (size_t)(m0 + am) * DM + ak;
    const float* Bg = W + (size_t)bk * LDIM + n0 + bn;

    unsigned long long acc[4][2];
#pragma unroll
    for (int i = 0; i < 4; i++) { acc[i][0] = 0ull; acc[i][1] = 0ull; }

    // prefetch kt=0
    float4 ra = *(const float4*)Ag;
    float4 rb = make_float4(0.f, 0.f, 0.f, 0.f);
    if (tid < 256) rb = *(const float4*)Bg;

#pragma unroll 1
    for (int kt = 0; kt < DM / 16; kt++) {
        const int buf = kt & 1;
        // store stage (duplicated A)
        float av[4] = {ra.x, ra.y, ra.z, ra.w};
#pragma unroll
        for (int j = 0; j < 4; j++) {
            float2 dup = make_float2(av[j], av[j]);
            *(float2*)&As[buf][(ak + j) * ADUP + 2 * am] = dup;
        }
        if (tid < 256) *(float4*)&Bs[buf][bk * BPAD + bn] = rb;
        __syncthreads();

        if (kt + 1 < DM / 16) {
            ra = *(const float4*)(Ag + (kt + 1) * 16);
            if (tid < 256) rb = *(const float4*)(Bg + (size_t)(kt + 1) * 16 * LDIM);
        }

#pragma unroll
        for (int k = 0; k < 16; k++) {
            ulonglong2 bb = *(const ulonglong2*)&Bs[buf][k * BPAD + tx * 4];
#pragma unroll
            for (int i = 0; i < 4; i++) {
                unsigned long long ap =
                    *(const unsigned long long*)&As[buf][k * ADUP + 2 * (ty * 4 + i)];
                acc[i][0] = fma2(ap, bb.x, acc[i][0]);
                acc[i][1] = fma2(ap, bb.y, acc[i][1]);
            }
        }
    }

    // fp16 epilogue
#pragma unroll
    for (int i = 0; i < 4; i++) {
        float x0, x1, x2, x3;
        unpk2(acc[i][0], x0, x1);
        unpk2(acc[i][1], x2, x3);
        __half2 h0 = __floats2half2_rn(x0, x1);
        __half2 h1 = __floats2half2_rn(x2, x3);
        uint2 o;
        o.x = *(unsigned*)&h0;
        o.y = *(unsigned*)&h1;
        *(uint2*)(Y + (size_t)(m0 + ty * 4 + i) * LDIM + n0 + tx * 4) = o;
    }
}

// =====================================================================
// Kernel B: fused scores + mask + log_softmax + transposed write.
// fp16 inputs, tanh.approx.f16x2 (2 tanh / MUFU op), fp32 accumulate.
// Grid (16, 8) = 128 blocks, 512 threads.
// Warp w: t-pair p=w>>1 (rows 2p,2p+1), s-half h=w&1, lane = s in half.
// s tiled in 4 tiles of 64 (double-buffered cp.async).
// smem (bytes):
//   sEt  half [2][64][264]  @ 0       67584
//   sDt  half [16][264]     @ 67584    8448
//   sVt  f32  [256]         @ 76032    1024
//   sSc  f32  [16][257]     @ 77056   16448
//   sLse f32  [16]          @ 93504      64
// total 93568 B
// =====================================================================
#define EPAD 264
#define SPAD 257
#define OFFB_DT  67584
#define OFFB_VT  76032
#define OFFB_SC  77056
#define OFFB_LSE 93504
#define SMEM_B_BYTES 93568

__device__ __forceinline__ void load_et64h(__half* dst, const __half* src, int tid) {
#pragma unroll
    for (int i = 0; i < 4; i++) {
        int idx = tid + i * 512;        // 0..2047 ; 64 rows x 32 chunks of 8 halves
        int r = idx >> 5, c = idx & 31;
        cp_async16(dst + r * EPAD + c * 8, src + r * LDIM + c * 8);
    }
    cp_commit();
}

// accumulate one f16x2 pair: a += tanh(d2+e2) . (vx,vy)
#define PAIR(acc, d2, e2, vx, vy)                               \
    {                                                           \
        float2 t_ = h2tof2(h2tanh(h2add((d2), (e2))));          \
        (acc) += t_.x * (vx);                                   \
        (acc) += t_.y * (vy);                                   \
    }

__global__ __launch_bounds__(512, 1) void attn_kernel(
    const int* __restrict__ lens, const float* __restrict__ vt,
    float* __restrict__ out)
{
    extern __shared__ char smc[];
    __half* sEt  = (__half*)smc;
    __half* sDt  = (__half*)(smc + OFFB_DT);
    float*  sVt  = (float*)(smc + OFFB_VT);
    float*  sSc  = (float*)(smc + OFFB_SC);
    float*  sLse = (float*)(smc + OFFB_LSE);

    const int tid = threadIdx.x;
    const int b   = blockIdx.y;
    const int t0  = blockIdx.x * 16;

    const __half* dtH = g_dt_h + ((size_t)b * TGT + t0) * LDIM;  // [16][256]
    const __half* etH = g_et_h + (size_t)b * SRC * LDIM;         // [256][256]

    // prefetch et tile 0 (async); dt + vt on sync path
    load_et64h(sEt, etH, tid);
    {   // 16 rows x 32 chunks = 512 uint4 ; 1 per thread
        int r = tid >> 5, c = tid & 31;
        *(uint4*)(sDt + r * EPAD + c * 8) = *(const uint4*)(dtH + r * LDIM + c * 8);
    }
    if (tid < 64) ((float4*)sVt)[tid] = ((const float4*)vt)[tid];

    cp_wait0();
    __syncthreads();

    const int w    = tid >> 5;
    const int lane = tid & 31;
    const int p    = w >> 1;            // t-pair 0..7
    const int h    = w & 1;             // s-half 0/1
    const __half* dR0 = sDt + (2 * p) * EPAD;
    const __half* dR1 = sDt + (2 * p + 1) * EPAD;

#pragma unroll 1
    for (int st = 0; st < 4; st++) {
        const __half* cur = sEt + (st & 1) * (64 * EPAD);
        if (st < 3)
            load_et64h(sEt + ((st + 1) & 1) * (64 * EPAD),
                       etH + (st + 1) * 64 * LDIM, tid);

        const __half* eR = cur + (h * 32 + lane) * EPAD;
        float a0 = 0.f, a1 = 0.f;
#pragma unroll 4
        for (int l = 0; l < 256; l += 8) {
            uint4 e  = *(const uint4*)(eR  + l);
            uint4 da = *(const uint4*)(dR0 + l);
            uint4 db = *(const uint4*)(dR1 + l);
            float4 v0 = *(const float4*)&sVt[l];
            float4 v1 = *(const float4*)&sVt[l + 4];

            PAIR(a0, da.x, e.x, v0.x, v0.y);
            PAIR(a1, db.x, e.x, v0.x, v0.y);
            PAIR(a0, da.y, e.y, v0.z, v0.w);
            PAIR(a1, db.y, e.y, v0.z, v0.w);
            PAIR(a0, da.z, e.z, v1.x, v1.y);
            PAIR(a1, db.z, e.z, v1.x, v1.y);
            PAIR(a0, da.w, e.w, v1.z, v1.w);
            PAIR(a1, db.w, e.w, v1.z, v1.w);
        }

        const int sg = st * 64 + h * 32 + lane;
        sSc[(2 * p) * SPAD + sg]     = a0;
        sSc[(2 * p + 1) * SPAD + sg] = a1;

        if (st < 3) cp_wait0();
        __syncthreads();
    }

    // ---- masked log_softmax over s: warp w handles row w (w<16) ----
    const int len = lens[b];
    if (w < 16) {
        float v[8];
        float mx = -3.0e38f;
#pragma unroll
        for (int i = 0; i < 8; i++) {
            int s = lane + 32 * i;
            float x = sSc[w * SPAD + s];
            if (s >= len) x += LOGEPS;
            v[i] = x;
            mx = fmaxf(mx, x);
        }
#pragma unroll
        for (int o = 16; o > 0; o >>= 1)
            mx = fmaxf(mx, __shfl_xor_sync(0xffffffffu, mx, o));
        float sum = 0.f;
#pragma unroll
        for (int i = 0; i < 8; i++) sum += __expf(v[i] - mx);
#pragma unroll
        for (int o = 16; o > 0; o >>= 1)
            sum += __shfl_xor_sync(0xffffffffu, sum, o);
        if (lane == 0) sLse[w] = mx + __logf(sum);
    }
    __syncthreads();

    // ---- transposed write: out[b][s][t0+lt] ----
    float* outB = out + (size_t)b * SRC * TGT + t0;
    const int lt = tid & 15;
    const int sB = tid >> 4;            // 0..31
    const float lse = sLse[lt];
#pragma unroll
    for (int pp = 0; pp < 8; pp++) {
        int s = sB + pp * 32;
        float x = sSc[lt * SPAD + s];
        if (s >= len) x += LOGEPS;
        outB[(size_t)s * TGT + lt] = x - lse;
    }
}

// =====================================================================
// launcher
// =====================================================================
extern "C" void kernel_launch(void* const* d_in, const int* in_sizes, int n_in,
                              void* d_out, int out_size)
{
    const float* dec = (const float*)d_in[0];   // [8,256,512]
    const float* enc = (const float*)d_in[1];   // [8,256,512]
    const int*   len = (const int*)  d_in[2];   // [8]
    const float* W1  = (const float*)d_in[3];   // [512,256]
    const float* W2  = (const float*)d_in[4];   // [512,256]
    const float* vt  = (const float*)d_in[5];   // [256]
    float* out = (float*)d_out;                 // [8,256,256] = [b][s][t]

    (void)in_sizes; (void)n_in; (void)out_size;

    cudaFuncSetAttribute(attn_kernel,
                         cudaFuncAttributeMaxDynamicSharedMemorySize,
                         SMEM_B_BYTES);

    dim3 gGemm(LDIM / 64, (B_ * TGT) / 128, 2);  // (4, 16, 2) = 128 blocks
    gemm_kernel<<<gGemm, 512>>>(dec, enc, W1, W2);

    dim3 gAttn(TGT / 16, B_);                    // (16, 8) = 128 blocks
    attn_kernel<<<gAttn, 512, SMEM_B_BYTES>>>(len, vt, out);
}

// round 8
// speedup vs baseline: 1.5866x; 1.5866x over previous
#include <cuda_runtime.h>
#include <cuda_fp16.h>
#include <cstdint>

// Problem constants
#define B_   8
#define TGT  256
#define SRC  256
#define DM   512
#define LDIM 256
#define LOGEPS (-18.420680743952367f)   // log(1e-8)

// -------- scratch (device globals; no allocation) --------
__device__ __half g_dt_h[B_ * TGT * LDIM];   // fp16(dec @ W1)
__device__ __half g_et_h[B_ * SRC * LDIM];   // fp16(enc @ W2)

// ---------------- helpers ----------------
__device__ __forceinline__ unsigned h2tanh(unsigned x) {
    unsigned y;
    asm("tanh.approx.f16x2 %0, %1;" : "=r"(y) : "r"(x));
    return y;
}
__device__ __forceinline__ unsigned h2add(unsigned a, unsigned b) {
    unsigned y;
    asm("add.rn.f16x2 %0, %1, %2;" : "=r"(y) : "r"(a), "r"(b));
    return y;
}
__device__ __forceinline__ float2 h2tof2(unsigned h) {
    float lo, hi;
    asm("{ .reg .b16 l, h;\n\t"
        "  mov.b32 {l, h}, %2;\n\t"
        "  cvt.f32.f16 %0, l;\n\t"
        "  cvt.f32.f16 %1, h; }"
        : "=f"(lo), "=f"(hi) : "r"(h));
    return make_float2(lo, hi);
}
__device__ __forceinline__ void cp_async16(void* smem_dst, const void* gmem_src) {
    unsigned saddr = (unsigned)__cvta_generic_to_shared(smem_dst);
    asm volatile("cp.async.ca.shared.global [%0], [%1], 16;"
                 :: "r"(saddr), "l"(gmem_src));
}
__device__ __forceinline__ void cp_commit() {
    asm volatile("cp.async.commit_group;" ::: "memory");
}
__device__ __forceinline__ void cp_wait0() {
    asm volatile("cp.async.wait_group 0;" ::: "memory");
}
__device__ __forceinline__ void mma16816(float& c0, float& c1, float& c2, float& c3,
                                         unsigned a0, unsigned a1, unsigned a2, unsigned a3,
                                         unsigned b0, unsigned b1) {
    asm volatile(
        "mma.sync.aligned.m16n8k16.row.col.f32.f16.f16.f32 "
        "{%0,%1,%2,%3},{%4,%5,%6,%7},{%8,%9},{%0,%1,%2,%3};"
        : "+f"(c0), "+f"(c1), "+f"(c2), "+f"(c3)
        : "r"(a0), "r"(a1), "r"(a2), "r"(a3), "r"(b0), "r"(b1));
}

// =====================================================================
// Kernel A (HMMA): Yh = fp16(X @ W).  X:[2048,512] fp32, W:[512,256] fp32
// Block 256 thr = 8 warps (4 m-warps x 2 n-warps). Block tile M=128,N=64.
// Warp tile m32 x n32. BK=32, 16 k-tiles, double-buffered smem.
// fp32 gmem -> cvt fp16 -> smem; mma.sync m16n8k16 (fp32 accum).
// Grid (4, 16, 2) = 128 blocks = 1 wave.
// =====================================================================
#define APADH 40   // halves per A smem row (32 k + 8 pad)  -> 80 B
#define BPADH 34   // halves per Bt smem row (32 k + 2 pad) -> 68 B

__global__ __launch_bounds__(256) void gemm_kernel(
    const float* __restrict__ dec, const float* __restrict__ enc,
    const float* __restrict__ W1,  const float* __restrict__ W2)
{
    const float* X; const float* W; __half* Y;
    if (blockIdx.z == 0) { X = dec; W = W1; Y = g_dt_h; }
    else                 { X = enc; W = W2; Y = g_et_h; }

    __shared__ __half Ah[2][128 * APADH];
    __shared__ __half Bt[2][64 * BPADH];   // transposed: [n][k]

    const int tid  = threadIdx.x;
    const int warp = tid >> 5;
    const int lane = tid & 31;
    const int mw   = warp & 3;            // 0..3
    const int nw   = warp >> 2;           // 0..1
    const int g    = lane >> 2;           // 0..7
    const int tig  = lane & 3;            // 0..3

    const int m0 = blockIdx.y * 128;
    const int n0 = blockIdx.x * 64;

    // staging assignments
    const int ar0 = tid >> 3;             // A row base (0..31), +32*i
    const int ac4 = tid & 7;              // A float4 col (k/4)
    const int bk0 = tid >> 4;             // B k-row base (0..15), +16*i
    const int bn4 = tid & 15;             // B float4 col (n/4)

    float4 ra[4], rb[2];

    auto loadRegs = [&](int kt) {
#pragma unroll
        for (int i = 0; i < 4; i++)
            ra[i] = *(const float4*)(X + (size_t)(m0 + ar0 + 32 * i) * DM
                                       + kt * 32 + ac4 * 4);
#pragma unroll
        for (int i = 0; i < 2; i++)
            rb[i] = *(const float4*)(W + (size_t)(kt * 32 + bk0 + 16 * i) * LDIM
                                       + n0 + bn4 * 4);
    };
    auto storeRegs = [&](int buf) {
#pragma unroll
        for (int i = 0; i < 4; i++) {
            __half2 h0 = __floats2half2_rn(ra[i].x, ra[i].y);
            __half2 h1 = __floats2half2_rn(ra[i].z, ra[i].w);
            uint2 u; u.x = *(unsigned*)&h0; u.y = *(unsigned*)&h1;
            *(uint2*)&Ah[buf][(ar0 + 32 * i) * APADH + ac4 * 4] = u;
        }
#pragma unroll
        for (int i = 0; i < 2; i++) {
            const int kk = bk0 + 16 * i;
            Bt[buf][(bn4 * 4 + 0) * BPADH + kk] = __float2half_rn(rb[i].x);
            Bt[buf][(bn4 * 4 + 1) * BPADH + kk] = __float2half_rn(rb[i].y);
            Bt[buf][(bn4 * 4 + 2) * BPADH + kk] = __float2half_rn(rb[i].z);
            Bt[buf][(bn4 * 4 + 3) * BPADH + kk] = __float2half_rn(rb[i].w);
        }
    };

    float acc[2][4][4];
#pragma unroll
    for (int a = 0; a < 2; a++)
#pragma unroll
        for (int b = 0; b < 4; b++)
#pragma unroll
            for (int c = 0; c < 4; c++) acc[a][b][c] = 0.f;

    loadRegs(0);
    storeRegs(0);
    __syncthreads();

#pragma unroll 1
    for (int kt = 0; kt < 16; kt++) {
        const int buf = kt & 1;
        if (kt < 15) loadRegs(kt + 1);

#pragma unroll
        for (int ks = 0; ks < 2; ks++) {
            const int kb = ks * 16 + 2 * tig;
            // B fragments: 4 n8 frags for this warp's n32
            unsigned bfr[4][2];
#pragma unroll
            for (int nf = 0; nf < 4; nf++) {
                const __half* bp = &Bt[buf][(nw * 32 + nf * 8 + g) * BPADH + kb];
                bfr[nf][0] = *(const unsigned*)bp;
                bfr[nf][1] = *(const unsigned*)(bp + 8);
            }
#pragma unroll
            for (int mf = 0; mf < 2; mf++) {
                const __half* ap = &Ah[buf][(mw * 32 + mf * 16 + g) * APADH + kb];
                unsigned a0 = *(const unsigned*)ap;
                unsigned a1 = *(const unsigned*)(ap + 8 * APADH);
                unsigned a2 = *(const unsigned*)(ap + 8);
                unsigned a3 = *(const unsigned*)(ap + 8 * APADH + 8);
#pragma unroll
                for (int nf = 0; nf < 4; nf++)
                    mma16816(acc[mf][nf][0], acc[mf][nf][1],
                             acc[mf][nf][2], acc[mf][nf][3],
                             a0, a1, a2, a3, bfr[nf][0], bfr[nf][1]);
            }
        }

        if (kt < 15) {
            storeRegs(buf ^ 1);
            __syncthreads();
        }
    }

    // fp16 epilogue
#pragma unroll
    for (int mf = 0; mf < 2; mf++) {
#pragma unroll
        for (int nf = 0; nf < 4; nf++) {
            const int row0 = m0 + mw * 32 + mf * 16 + g;
            const int col  = n0 + nw * 32 + nf * 8 + 2 * tig;
            __half2 h01 = __floats2half2_rn(acc[mf][nf][0], acc[mf][nf][1]);
            __half2 h23 = __floats2half2_rn(acc[mf][nf][2], acc[mf][nf][3]);
            *(unsigned*)(Y + (size_t)row0 * LDIM + col)       = *(unsigned*)&h01;
            *(unsigned*)(Y + (size_t)(row0 + 8) * LDIM + col) = *(unsigned*)&h23;
        }
    }
}

// =====================================================================
// Kernel B: fused scores + mask + log_softmax + transposed write.
// (unchanged from R7: fp16 inputs, tanh.approx.f16x2, fp32 accumulate)
// Grid (16, 8) = 128 blocks, 512 threads.
// =====================================================================
#define EPAD 264
#define SPAD 257
#define OFFB_DT  67584
#define OFFB_VT  76032
#define OFFB_SC  77056
#define OFFB_LSE 93504
#define SMEM_B_BYTES 93568

__device__ __forceinline__ void load_et64h(__half* dst, const __half* src, int tid) {
#pragma unroll
    for (int i = 0; i < 4; i++) {
        int idx = tid + i * 512;        // 64 rows x 32 chunks of 8 halves
        int r = idx >> 5, c = idx & 31;
        cp_async16(dst + r * EPAD + c * 8, src + r * LDIM + c * 8);
    }
    cp_commit();
}

#define PAIR(acc, d2, e2, vx, vy)                               \
    {                                                           \
        float2 t_ = h2tof2(h2tanh(h2add((d2), (e2))));          \
        (acc) += t_.x * (vx);                                   \
        (acc) += t_.y * (vy);                                   \
    }

__global__ __launch_bounds__(512, 1) void attn_kernel(
    const int* __restrict__ lens, const float* __restrict__ vt,
    float* __restrict__ out)
{
    extern __shared__ char smc[];
    __half* sEt  = (__half*)smc;
    __half* sDt  = (__half*)(smc + OFFB_DT);
    float*  sVt  = (float*)(smc + OFFB_VT);
    float*  sSc  = (float*)(smc + OFFB_SC);
    float*  sLse = (float*)(smc + OFFB_LSE);

    const int tid = threadIdx.x;
    const int b   = blockIdx.y;
    const int t0  = blockIdx.x * 16;

    const __half* dtH = g_dt_h + ((size_t)b * TGT + t0) * LDIM;
    const __half* etH = g_et_h + (size_t)b * SRC * LDIM;

    load_et64h(sEt, etH, tid);
    {
        int r = tid >> 5, c = tid & 31;
        *(uint4*)(sDt + r * EPAD + c * 8) = *(const uint4*)(dtH + r * LDIM + c * 8);
    }
    if (tid < 64) ((float4*)sVt)[tid] = ((const float4*)vt)[tid];

    cp_wait0();
    __syncthreads();

    const int w    = tid >> 5;
    const int lane = tid & 31;
    const int p    = w >> 1;
    const int h    = w & 1;
    const __half* dR0 = sDt + (2 * p) * EPAD;
    const __half* dR1 = sDt + (2 * p + 1) * EPAD;

#pragma unroll 1
    for (int st = 0; st < 4; st++) {
        const __half* cur = sEt + (st & 1) * (64 * EPAD);
        if (st < 3)
            load_et64h(sEt + ((st + 1) & 1) * (64 * EPAD),
                       etH + (st + 1) * 64 * LDIM, tid);

        const __half* eR = cur + (h * 32 + lane) * EPAD;
        float a0 = 0.f, a1 = 0.f;
#pragma unroll 4
        for (int l = 0; l < 256; l += 8) {
            uint4 e  = *(const uint4*)(eR  + l);
            uint4 da = *(const uint4*)(dR0 + l);
            uint4 db = *(const uint4*)(dR1 + l);
            float4 v0 = *(const float4*)&sVt[l];
            float4 v1 = *(const float4*)&sVt[l + 4];

            PAIR(a0, da.x, e.x, v0.x, v0.y);
            PAIR(a1, db.x, e.x, v0.x, v0.y);
            PAIR(a0, da.y, e.y, v0.z, v0.w);
            PAIR(a1, db.y, e.y, v0.z, v0.w);
            PAIR(a0, da.z, e.z, v1.x, v1.y);
            PAIR(a1, db.z, e.z, v1.x, v1.y);
            PAIR(a0, da.w, e.w, v1.z, v1.w);
            PAIR(a1, db.w, e.w, v1.z, v1.w);
        }

        const int sg = st * 64 + h * 32 + lane;
        sSc[(2 * p) * SPAD + sg]     = a0;
        sSc[(2 * p + 1) * SPAD + sg] = a1;

        if (st < 3) cp_wait0();
        __syncthreads();
    }

    const int len = lens[b];
    if (w < 16) {
        float v[8];
        float mx = -3.0e38f;
#pragma unroll
        for (int i = 0; i < 8; i++) {
            int s = lane + 32 * i;
            float x = sSc[w * SPAD + s];
            if (s >= len) x += LOGEPS;
            v[i] = x;
            mx = fmaxf(mx, x);
        }
#pragma unroll
        for (int o = 16; o > 0; o >>= 1)
            mx = fmaxf(mx, __shfl_xor_sync(0xffffffffu, mx, o));
        float sum = 0.f;
#pragma unroll
        for (int i = 0; i < 8; i++) sum += __expf(v[i] - mx);
#pragma unroll
        for (int o = 16; o > 0; o >>= 1)
            sum += __shfl_xor_sync(0xffffffffu, sum, o);
        if (lane == 0) sLse[w] = mx + __logf(sum);
    }
    __syncthreads();

    float* outB = out + (size_t)b * SRC * TGT + t0;
    const int lt = tid & 15;
    const int sB = tid >> 4;
    const float lse = sLse[lt];
#pragma unroll
    for (int pp = 0; pp < 8; pp++) {
        int s = sB + pp * 32;
        float x = sSc[lt * SPAD + s];
        if (s >= len) x += LOGEPS;
        outB[(size_t)s * TGT + lt] = x - lse;
    }
}

// =====================================================================
// launcher
// =====================================================================
extern "C" void kernel_launch(void* const* d_in, const int* in_sizes, int n_in,
                              void* d_out, int out_size)
{
    const float* dec = (const float*)d_in[0];   // [8,256,512]
    const float* enc = (const float*)d_in[1];   // [8,256,512]
    const int*   len = (const int*)  d_in[2];   // [8]
    const float* W1  = (const float*)d_in[3];   // [512,256]
    const float* W2  = (const float*)d_in[4];   // [512,256]
    const float* vt  = (const float*)d_in[5];   // [256]
    float* out = (float*)d_out;                 // [8,256,256] = [b][s][t]

    (void)in_sizes; (void)n_in; (void)out_size;

    cudaFuncSetAttribute(attn_kernel,
                         cudaFuncAttributeMaxDynamicSharedMemorySize,
                         SMEM_B_BYTES);

    dim3 gGemm(LDIM / 64, (B_ * TGT) / 128, 2);  // (4, 16, 2) = 128 blocks
    gemm_kernel<<<gGemm, 256>>>(dec, enc, W1, W2);

    dim3 gAttn(TGT / 16, B_);                    // (16, 8) = 128 blocks
    attn_kernel<<<gAttn, 512, SMEM_B_BYTES>>>(len, vt, out);
}

// round 9
// speedup vs baseline: 1.5944x; 1.0050x over previous
#include <cuda_runtime.h>
#include <cuda_fp16.h>
#include <cstdint>

// Problem constants
#define B_   8
#define TGT  256
#define SRC  256
#define DM   512
#define LDIM 256
#define LOGEPS (-18.420680743952367f)   // log(1e-8)

// -------- scratch (device globals; no allocation) --------
__device__ __half g_dt_h[B_ * TGT * LDIM];   // fp16(dec @ W1)
__device__ __half g_et_h[B_ * SRC * LDIM];   // fp16(enc @ W2)

// ---------------- helpers ----------------
__device__ __forceinline__ unsigned h2tanh(unsigned x) {
    unsigned y;
    asm("tanh.approx.f16x2 %0, %1;" : "=r"(y) : "r"(x));
    return y;
}
__device__ __forceinline__ unsigned h2add(unsigned a, unsigned b) {
    unsigned y;
    asm("add.rn.f16x2 %0, %1, %2;" : "=r"(y) : "r"(a), "r"(b));
    return y;
}
__device__ __forceinline__ float2 h2tof2(unsigned h) {
    float lo, hi;
    asm("{ .reg .b16 l, h;\n\t"
        "  mov.b32 {l, h}, %2;\n\t"
        "  cvt.f32.f16 %0, l;\n\t"
        "  cvt.f32.f16 %1, h; }"
        : "=f"(lo), "=f"(hi) : "r"(h));
    return make_float2(lo, hi);
}
__device__ __forceinline__ void cp_async16(void* smem_dst, const void* gmem_src) {
    unsigned saddr = (unsigned)__cvta_generic_to_shared(smem_dst);
    asm volatile("cp.async.ca.shared.global [%0], [%1], 16;"
                 :: "r"(saddr), "l"(gmem_src));
}
__device__ __forceinline__ void cp_commit() {
    asm volatile("cp.async.commit_group;" ::: "memory");
}
__device__ __forceinline__ void cp_wait0() {
    asm volatile("cp.async.wait_group 0;" ::: "memory");
}
__device__ __forceinline__ void mma16816(float& c0, float& c1, float& c2, float& c3,
                                         unsigned a0, unsigned a1, unsigned a2, unsigned a3,
                                         unsigned b0, unsigned b1) {
    asm volatile(
        "mma.sync.aligned.m16n8k16.row.col.f32.f16.f16.f32 "
        "{%0,%1,%2,%3},{%4,%5,%6,%7},{%8,%9},{%0,%1,%2,%3};"
        : "+f"(c0), "+f"(c1), "+f"(c2), "+f"(c3)
        : "r"(a0), "r"(a1), "r"(a2), "r"(a3), "r"(b0), "r"(b1));
}

// =====================================================================
// Kernel A (HMMA): Yh = fp16(X @ W).  Unchanged from R8 (measured ~9us).
// =====================================================================
#define APADH 40
#define BPADH 34

__global__ __launch_bounds__(256) void gemm_kernel(
    const float* __restrict__ dec, const float* __restrict__ enc,
    const float* __restrict__ W1,  const float* __restrict__ W2)
{
    const float* X; const float* W; __half* Y;
    if (blockIdx.z == 0) { X = dec; W = W1; Y = g_dt_h; }
    else                 { X = enc; W = W2; Y = g_et_h; }

    __shared__ __half Ah[2][128 * APADH];
    __shared__ __half Bt[2][64 * BPADH];   // transposed: [n][k]

    const int tid  = threadIdx.x;
    const int warp = tid >> 5;
    const int lane = tid & 31;
    const int mw   = warp & 3;
    const int nw   = warp >> 2;
    const int g    = lane >> 2;
    const int tig  = lane & 3;

    const int m0 = blockIdx.y * 128;
    const int n0 = blockIdx.x * 64;

    const int ar0 = tid >> 3;
    const int ac4 = tid & 7;
    const int bk0 = tid >> 4;
    const int bn4 = tid & 15;

    float4 ra[4], rb[2];

    auto loadRegs = [&](int kt) {
#pragma unroll
        for (int i = 0; i < 4; i++)
            ra[i] = *(const float4*)(X + (size_t)(m0 + ar0 + 32 * i) * DM
                                       + kt * 32 + ac4 * 4);
#pragma unroll
        for (int i = 0; i < 2; i++)
            rb[i] = *(const float4*)(W + (size_t)(kt * 32 + bk0 + 16 * i) * LDIM
                                       + n0 + bn4 * 4);
    };
    auto storeRegs = [&](int buf) {
#pragma unroll
        for (int i = 0; i < 4; i++) {
            __half2 h0 = __floats2half2_rn(ra[i].x, ra[i].y);
            __half2 h1 = __floats2half2_rn(ra[i].z, ra[i].w);
            uint2 u; u.x = *(unsigned*)&h0; u.y = *(unsigned*)&h1;
            *(uint2*)&Ah[buf][(ar0 + 32 * i) * APADH + ac4 * 4] = u;
        }
#pragma unroll
        for (int i = 0; i < 2; i++) {
            const int kk = bk0 + 16 * i;
            Bt[buf][(bn4 * 4 + 0) * BPADH + kk] = __float2half_rn(rb[i].x);
            Bt[buf][(bn4 * 4 + 1) * BPADH + kk] = __float2half_rn(rb[i].y);
            Bt[buf][(bn4 * 4 + 2) * BPADH + kk] = __float2half_rn(rb[i].z);
            Bt[buf][(bn4 * 4 + 3) * BPADH + kk] = __float2half_rn(rb[i].w);
        }
    };

    float acc[2][4][4];
#pragma unroll
    for (int a = 0; a < 2; a++)
#pragma unroll
        for (int b = 0; b < 4; b++)
#pragma unroll
            for (int c = 0; c < 4; c++) acc[a][b][c] = 0.f;

    loadRegs(0);
    storeRegs(0);
    __syncthreads();

#pragma unroll 1
    for (int kt = 0; kt < 16; kt++) {
        const int buf = kt & 1;
        if (kt < 15) loadRegs(kt + 1);

#pragma unroll
        for (int ks = 0; ks < 2; ks++) {
            const int kb = ks * 16 + 2 * tig;
            unsigned bfr[4][2];
#pragma unroll
            for (int nf = 0; nf < 4; nf++) {
                const __half* bp = &Bt[buf][(nw * 32 + nf * 8 + g) * BPADH + kb];
                bfr[nf][0] = *(const unsigned*)bp;
                bfr[nf][1] = *(const unsigned*)(bp + 8);
            }
#pragma unroll
            for (int mf = 0; mf < 2; mf++) {
                const __half* ap = &Ah[buf][(mw * 32 + mf * 16 + g) * APADH + kb];
                unsigned a0 = *(const unsigned*)ap;
                unsigned a1 = *(const unsigned*)(ap + 8 * APADH);
                unsigned a2 = *(const unsigned*)(ap + 8);
                unsigned a3 = *(const unsigned*)(ap + 8 * APADH + 8);
#pragma unroll
                for (int nf = 0; nf < 4; nf++)
                    mma16816(acc[mf][nf][0], acc[mf][nf][1],
                             acc[mf][nf][2], acc[mf][nf][3],
                             a0, a1, a2, a3, bfr[nf][0], bfr[nf][1]);
            }
        }

        if (kt < 15) {
            storeRegs(buf ^ 1);
            __syncthreads();
        }
    }

#pragma unroll
    for (int mf = 0; mf < 2; mf++) {
#pragma unroll
        for (int nf = 0; nf < 4; nf++) {
            const int row0 = m0 + mw * 32 + mf * 16 + g;
            const int col  = n0 + nw * 32 + nf * 8 + 2 * tig;
            __half2 h01 = __floats2half2_rn(acc[mf][nf][0], acc[mf][nf][1]);
            __half2 h23 = __floats2half2_rn(acc[mf][nf][2], acc[mf][nf][3]);
            *(unsigned*)(Y + (size_t)row0 * LDIM + col)       = *(unsigned*)&h01;
            *(unsigned*)(Y + (size_t)(row0 + 8) * LDIM + col) = *(unsigned*)&h23;
        }
    }
}

// =====================================================================
// Kernel B v3: t-tile 2, 1024 blocks, occ 2 (8 warps/SMSP).
// Block = 2 t-rows of batch b. Warp w: t-row r=w&1, s-strip (w>>1)*32;
// lane owns one s, one fp32 accumulator, sweeping l in 4 tiles of 64.
// et chunk [256 s][64 l] fp16, padded row stride 72 halves (144 B:
// 16B-chunk stride 9 = odd -> conflict-free LDS.128), double-buffered.
// smem bytes:
//   sEt  [2][256*72]h  @ 0      73728
//   sDt  [2*256]h      @ 73728   1024
//   sVt  [256]f        @ 74752   1024
//   sSc  [2][257]f     @ 75776    2080 (padded)
//   sLse [2]f          @ 77856      32 (padded)
// total 77888 B -> 2 blocks/SM
// =====================================================================
#define EPAD2 72
#define ETILE (256 * EPAD2)          // halves per buffer
#define OFF2_DT  73728
#define OFF2_VT  74752
#define OFF2_SC  75776
#define OFF2_LSE 77856
#define SMEM_B2_BYTES 77888

__device__ __forceinline__ void load_et_chunk(__half* dst, const __half* src,
                                              int l0, int tid) {
#pragma unroll
    for (int i = 0; i < 4; i++) {
        int idx = tid + i * 512;        // 0..2047: 256 rows x 8 chunks of 8 halves
        int r = idx >> 3, c = idx & 7;
        cp_async16(dst + r * EPAD2 + c * 8, src + r * LDIM + l0 + c * 8);
    }
    cp_commit();
}

#define PAIR1(acc, d2, e2, vx, vy)                              \
    {                                                           \
        float2 t_ = h2tof2(h2tanh(h2add((d2), (e2))));          \
        (acc) += t_.x * (vx);                                   \
        (acc) += t_.y * (vy);                                   \
    }

__global__ __launch_bounds__(512, 2) void attn_kernel(
    const int* __restrict__ lens, const float* __restrict__ vt,
    float* __restrict__ out)
{
    extern __shared__ char smc[];
    __half* sEt  = (__half*)smc;
    __half* sDt  = (__half*)(smc + OFF2_DT);
    float*  sVt  = (float*)(smc + OFF2_VT);
    float*  sSc  = (float*)(smc + OFF2_SC);
    float*  sLse = (float*)(smc + OFF2_LSE);

    const int tid = threadIdx.x;
    const int b   = blockIdx.y;
    const int t0  = blockIdx.x * 2;

    const __half* dtH = g_dt_h + ((size_t)b * TGT + t0) * LDIM;  // [2][256]
    const __half* etH = g_et_h + (size_t)b * SRC * LDIM;         // [256][256]

    // prefetch et l-tile 0 (async); dt + vt on sync path
    load_et_chunk(sEt, etH, 0, tid);
    if (tid < 64) {
        *(uint4*)(sDt + tid * 8) = *(const uint4*)(dtH + tid * 8);   // 512 halves
        ((float4*)sVt)[tid] = ((const float4*)vt)[tid];
    }
    cp_wait0();
    __syncthreads();

    const int w    = tid >> 5;
    const int lane = tid & 31;
    const int r    = w & 1;                 // t-row in pair
    const int s    = (w >> 1) * 32 + lane;  // this lane's source position
    const __half* dR = sDt + r * 256;
    const __half* eRbase = sEt + s * EPAD2;

    float acc = 0.f;

#pragma unroll 1
    for (int st = 0; st < 4; st++) {
        const __half* eR = eRbase + (st & 1) * ETILE;
        if (st < 3)
            load_et_chunk(sEt + ((st + 1) & 1) * ETILE, etH, (st + 1) * 64, tid);

        const int l0 = st * 64;
#pragma unroll
        for (int lc = 0; lc < 64; lc += 8) {
            uint4 e = *(const uint4*)(eR + lc);
            uint4 d = *(const uint4*)(dR + l0 + lc);     // warp-broadcast
            float4 v0 = *(const float4*)&sVt[l0 + lc];
            float4 v1 = *(const float4*)&sVt[l0 + lc + 4];

            PAIR1(acc, d.x, e.x, v0.x, v0.y);
            PAIR1(acc, d.y, e.y, v0.z, v0.w);
            PAIR1(acc, d.z, e.z, v1.x, v1.y);
            PAIR1(acc, d.w, e.w, v1.z, v1.w);
        }

        if (st < 3) cp_wait0();
        __syncthreads();
    }

    // stash raw scores
    sSc[r * 257 + s] = acc;
    __syncthreads();

    // ---- masked log_softmax: warp 0 -> row 0, warp 1 -> row 1 ----
    const int len = lens[b];
    if (w < 2) {
        float v[8];
        float mx = -3.0e38f;
#pragma unroll
        for (int i = 0; i < 8; i++) {
            int ss = lane + 32 * i;
            float x = sSc[w * 257 + ss];
            if (ss >= len) x += LOGEPS;
            v[i] = x;
            mx = fmaxf(mx, x);
        }
#pragma unroll
        for (int o = 16; o > 0; o >>= 1)
            mx = fmaxf(mx, __shfl_xor_sync(0xffffffffu, mx, o));
        float sum = 0.f;
#pragma unroll
        for (int i = 0; i < 8; i++) sum += __expf(v[i] - mx);
#pragma unroll
        for (int o = 16; o > 0; o >>= 1)
            sum += __shfl_xor_sync(0xffffffffu, sum, o);
        if (lane == 0) sLse[w] = mx + __logf(sum);
    }
    __syncthreads();

    // ---- transposed write: out[b][s][t0+lt], 512 threads cover 2x256 ----
    float* outB = out + (size_t)b * SRC * TGT + t0;
    const int lt = tid & 1;
    const int so = tid >> 1;
    float x = sSc[lt * 257 + so];
    if (so >= len) x += LOGEPS;
    outB[(size_t)so * TGT + lt] = x - sLse[lt];
}

// =====================================================================
// launcher
// =====================================================================
extern "C" void kernel_launch(void* const* d_in, const int* in_sizes, int n_in,
                              void* d_out, int out_size)
{
    const float* dec = (const float*)d_in[0];   // [8,256,512]
    const float* enc = (const float*)d_in[1];   // [8,256,512]
    const int*   len = (const int*)  d_in[2];   // [8]
    const float* W1  = (const float*)d_in[3];   // [512,256]
    const float* W2  = (const float*)d_in[4];   // [512,256]
    const float* vt  = (const float*)d_in[5];   // [256]
    float* out = (float*)d_out;                 // [8,256,256] = [b][s][t]

    (void)in_sizes; (void)n_in; (void)out_size;

    cudaFuncSetAttribute(attn_kernel,
                         cudaFuncAttributeMaxDynamicSharedMemorySize,
                         SMEM_B2_BYTES);

    dim3 gGemm(LDIM / 64, (B_ * TGT) / 128, 2);  // (4, 16, 2) = 128 blocks
    gemm_kernel<<<gGemm, 256>>>(dec, enc, W1, W2);

    dim3 gAttn(TGT / 2, B_);                     // (128, 8) = 1024 blocks
    attn_kernel<<<gAttn, 512, SMEM_B2_BYTES>>>(len, vt, out);
}